// round 2
// baseline (speedup 1.0000x reference)
#include <cuda_runtime.h>
#include <cstdint>

#define BB    2
#define CC    64
#define NPOS  131072
#define HEADS 4
#define DHEAD 32
#define HID   128
#define TPB   256

typedef unsigned long long u64;

// ---------------- device scratch (static, allowed) ----------------
__device__ float g_q[(size_t)BB * HID * NPOS];         // softmaxed+scaled q, [b][h*32+d][n]
__device__ float g_ctx[BB * HEADS * DHEAD * DHEAD];    // raw sum exp(k_d)*v_e
__device__ float g_Z[BB * HEADS * DHEAD];              // sum exp(k_d)
__device__ float g_M[BB * CC * HID];                   // folded  W_out x (ctx/Z)

// ---------------- f32x2 helpers ----------------
__device__ __forceinline__ u64 pack2(float lo, float hi) {
    u64 r; asm("mov.b64 %0, {%1,%2};" : "=l"(r) : "f"(lo), "f"(hi)); return r;
}
__device__ __forceinline__ u64 ffma2(u64 a, u64 b, u64 c) {
    u64 d; asm("fma.rn.f32x2 %0, %1, %2, %3;" : "=l"(d) : "l"(a), "l"(b), "l"(c)); return d;
}
__device__ __forceinline__ u64 fadd2(u64 a, u64 b) {
    u64 d; asm("add.rn.f32x2 %0, %1, %2;" : "=l"(d) : "l"(a), "l"(b)); return d;
}
__device__ __forceinline__ float hsum2(u64 a) {
    float lo, hi; asm("mov.b64 {%0,%1}, %2;" : "=f"(lo), "=f"(hi) : "l"(a)); return lo + hi;
}

// 64-length dot: W row (smem, packed as pairs) . xp (regs, packed pairs)
__device__ __forceinline__ float dot64(const float* __restrict__ wrow, const u64* __restrict__ xp) {
    const ulonglong2* wp = (const ulonglong2*)wrow;
    u64 a0 = 0, a1 = 0, a2 = 0, a3 = 0;
#pragma unroll
    for (int i = 0; i < 8; i++) {
        ulonglong2 w0 = wp[2 * i];
        ulonglong2 w1 = wp[2 * i + 1];
        a0 = ffma2(w0.x, xp[4 * i + 0], a0);
        a1 = ffma2(w0.y, xp[4 * i + 1], a1);
        a2 = ffma2(w1.x, xp[4 * i + 2], a2);
        a3 = ffma2(w1.y, xp[4 * i + 3], a3);
    }
    return hsum2(fadd2(fadd2(a0, a1), fadd2(a2, a3)));
}

// ---------------- kernel 0: zero accumulators ----------------
__global__ void la_zero_kernel() {
    int i = blockIdx.x * blockDim.x + threadIdx.x;
    if (i < BB * HEADS * DHEAD * DHEAD) g_ctx[i] = 0.f;
    if (i < BB * HEADS * DHEAD)         g_Z[i]   = 0.f;
}

// ---------------- kernel 1: LN1 + qkv matvec + q softmax + ctx/Z partials ----------------
// smem: Wc[2048] g1s[64] b1s[64] ek[32*260] vv[32*260]  = 18816 floats = 75264 B
#define SM1_FLOATS (2048 + 64 + 64 + 32 * 260 + 32 * 260)

__device__ __forceinline__ void loadW(float* Wc, const float* __restrict__ src, int t) {
    __syncthreads();                       // prior consumers of Wc / tiles done
#pragma unroll
    for (int i = 0; i < 2; i++)
        ((float4*)Wc)[t + i * 256] = ((const float4*)src)[t + i * 256];
    __syncthreads();                       // chunk ready
}

__global__ __launch_bounds__(TPB, 2)
void la_pass1_kernel(const float* __restrict__ x, const float* __restrict__ g1,
                     const float* __restrict__ b1, const float* __restrict__ wqkv) {
    extern __shared__ float sm1[];
    float* Wc  = sm1;                // 2048
    float* g1s = Wc + 2048;          // 64
    float* b1s = g1s + 64;           // 64
    float* ek  = b1s + 64;           // 32*260  (also q scratch)
    float* vv  = ek + 32 * 260;      // 32*260

    const int t   = threadIdx.x;
    const int bb  = blockIdx.y;
    const int pos = blockIdx.x * TPB + t;

    if (t < 64) { g1s[t] = g1[t]; b1s[t] = b1[t]; }

    // ---- load x column, layernorm stats ----
    const float* xb = x + (size_t)bb * CC * NPOS + pos;
    float xr[64];
    float s = 0.f, s2 = 0.f;
#pragma unroll
    for (int c = 0; c < 64; c++) {
        float v = __ldg(xb + (size_t)c * NPOS);
        xr[c] = v; s += v; s2 += v * v;
    }
    float mean = s * (1.f / 64.f);
    float rstd = rsqrtf(s2 * (1.f / 64.f) - mean * mean + 1e-5f);
    __syncthreads();                       // g1s/b1s ready

    u64 xp[32];
#pragma unroll
    for (int i = 0; i < 32; i++) {
        float a  = (xr[2 * i]     - mean) * rstd * g1s[2 * i]     + b1s[2 * i];
        float bv = (xr[2 * i + 1] - mean) * rstd * g1s[2 * i + 1] + b1s[2 * i + 1];
        xp[i] = pack2(a, bv);
    }

    const int d_own = t >> 3;       // 0..31
    const int e0    = t & 7;        // 0..7

    for (int h = 0; h < HEADS; h++) {
        // ---------- Q ----------
        loadW(Wc, wqkv + (size_t)(h * 32) * 64, t);
        for (int d = 0; d < 32; d++)
            ek[d * 260 + t] = dot64(Wc + d * 64, xp);
        // per-position softmax over d (own column only, no barrier needed)
        float mx = -1e30f;
        for (int d = 0; d < 32; d++) mx = fmaxf(mx, ek[d * 260 + t]);
        float ss = 0.f;
        for (int d = 0; d < 32; d++) {
            float e = __expf(ek[d * 260 + t] - mx);
            ek[d * 260 + t] = e; ss += e;
        }
        float qsc = 0.17677669529663687f / ss;     // DIM_HEAD^-0.5 / sum
        float* qg = g_q + (size_t)(bb * HID + h * 32) * NPOS + pos;
        for (int d = 0; d < 32; d++)
            qg[(size_t)d * NPOS] = ek[d * 260 + t] * qsc;

        // ---------- K (exp, no max subtraction; values ~N(0,1)) ----------
        loadW(Wc, wqkv + (size_t)(HID + h * 32) * 64, t);
        for (int d = 0; d < 32; d++)
            ek[d * 260 + t] = __expf(dot64(Wc + d * 64, xp));

        // ---------- V ----------
        loadW(Wc, wqkv + (size_t)(2 * HID + h * 32) * 64, t);
        for (int d = 0; d < 32; d++)
            vv[d * 260 + t] = dot64(Wc + d * 64, xp);
        __syncthreads();

        // ---------- stage B: ctx[d,e] += sum_tt ek[d,tt]*vv[e,tt], Z[d] += sum ek ----------
        u64 acc0 = 0, acc1 = 0, acc2 = 0, acc3 = 0, za = 0;
        const float* ekr = ek + d_own * 260;
#pragma unroll 4
        for (int tt = 0; tt < TPB; tt += 4) {
            ulonglong2 ap  = *(const ulonglong2*)(ekr + tt);
            ulonglong2 bv0 = *(const ulonglong2*)(vv + (e0     ) * 260 + tt);
            ulonglong2 bv1 = *(const ulonglong2*)(vv + (e0 +  8) * 260 + tt);
            ulonglong2 bv2 = *(const ulonglong2*)(vv + (e0 + 16) * 260 + tt);
            ulonglong2 bv3 = *(const ulonglong2*)(vv + (e0 + 24) * 260 + tt);
            acc0 = ffma2(ap.x, bv0.x, acc0); acc0 = ffma2(ap.y, bv0.y, acc0);
            acc1 = ffma2(ap.x, bv1.x, acc1); acc1 = ffma2(ap.y, bv1.y, acc1);
            acc2 = ffma2(ap.x, bv2.x, acc2); acc2 = ffma2(ap.y, bv2.y, acc2);
            acc3 = ffma2(ap.x, bv3.x, acc3); acc3 = ffma2(ap.y, bv3.y, acc3);
            if (e0 == 0) za = fadd2(za, fadd2(ap.x, ap.y));
        }
        float* cb = g_ctx + (size_t)((bb * HEADS + h) * DHEAD + d_own) * DHEAD;
        atomicAdd(cb + e0,      hsum2(acc0));
        atomicAdd(cb + e0 +  8, hsum2(acc1));
        atomicAdd(cb + e0 + 16, hsum2(acc2));
        atomicAdd(cb + e0 + 24, hsum2(acc3));
        if (e0 == 0) atomicAdd(g_Z + (bb * HEADS + h) * DHEAD + d_own, hsum2(za));
        // next head's loadW pre-sync protects tile reuse
    }
}

// ---------------- kernel 2: fold  M[o][h*32+d] = sum_e W_out[o][h*32+e] * ctx[h,d,e] / Z[h,d]
__global__ void la_fold_kernel(const float* __restrict__ wout) {
    int bb = blockIdx.x;
    for (int idx = threadIdx.x; idx < CC * HID; idx += blockDim.x) {
        int o  = idx >> 7;
        int hd = idx & 127;
        int h  = hd >> 5;
        int d  = hd & 31;
        const float* cp = g_ctx + (size_t)((bb * HEADS + h) * DHEAD + d) * DHEAD;
        const float* wp = wout + (size_t)o * HID + h * DHEAD;
        float acc = 0.f;
#pragma unroll
        for (int e = 0; e < 32; e++) acc += wp[e] * cp[e];
        g_M[(size_t)bb * CC * HID + idx] = acc / g_Z[(bb * HEADS + h) * DHEAD + d];
    }
}

// ---------------- kernel 3: y = LN2( M @ q + b_out ) ----------------
// smem: Ms[8192] bo[64] g2s[64] b2s[64] ys[64*256] = 24768 floats = 99072 B
#define SM2_FLOATS (8192 + 64 + 64 + 64 + 64 * TPB)

__global__ __launch_bounds__(TPB, 2)
void la_pass2_kernel(const float* __restrict__ bout, const float* __restrict__ g2,
                     const float* __restrict__ b2, float* __restrict__ out) {
    extern __shared__ float sm2[];
    float* Ms  = sm2;             // 8192
    float* bo  = Ms + 8192;       // 64
    float* g2s = bo + 64;         // 64
    float* b2s = g2s + 64;        // 64
    float* ys  = b2s + 64;        // 64*TPB (per-thread column, no cross-thread use)

    const int t   = threadIdx.x;
    const int bb  = blockIdx.y;
    const int pos = blockIdx.x * TPB + t;

    for (int i = t; i < (CC * HID) / 4; i += TPB)
        ((float4*)Ms)[i] = ((const float4*)(g_M + (size_t)bb * CC * HID))[i];
    if (t < 64) { bo[t] = bout[t]; g2s[t] = g2[t]; b2s[t] = b2[t]; }
    for (int o = 0; o < 64; o++) ys[o * TPB + t] = 0.f;
    __syncthreads();

    const float* qb = g_q + (size_t)bb * HID * NPOS + pos;
    for (int h = 0; h < HEADS; h++) {
        u64 qp[16];
#pragma unroll
        for (int i = 0; i < 16; i++) {
            float a = __ldg(qb + (size_t)(h * 32 + 2 * i)     * NPOS);
            float c = __ldg(qb + (size_t)(h * 32 + 2 * i + 1) * NPOS);
            qp[i] = pack2(a, c);
        }
        for (int o = 0; o < 64; o++) {
            const ulonglong2* mp = (const ulonglong2*)(Ms + o * HID + h * 32);
            u64 a0 = 0, a1 = 0;
#pragma unroll
            for (int i = 0; i < 8; i++) {
                ulonglong2 m = mp[i];
                a0 = ffma2(m.x, qp[2 * i],     a0);
                a1 = ffma2(m.y, qp[2 * i + 1], a1);
            }
            ys[o * TPB + t] += hsum2(fadd2(a0, a1));
        }
    }

    // final layernorm over channels
    float s = 0.f, s2 = 0.f;
    for (int o = 0; o < 64; o++) {
        float v = ys[o * TPB + t] + bo[o];
        s += v; s2 += v * v;
    }
    float mean = s * (1.f / 64.f);
    float rstd = rsqrtf(s2 * (1.f / 64.f) - mean * mean + 1e-5f);
    float* ob = out + (size_t)bb * CC * NPOS + pos;
    for (int o = 0; o < 64; o++) {
        float v = ys[o * TPB + t] + bo[o];
        ob[(size_t)o * NPOS] = (v - mean) * rstd * g2s[o] + b2s[o];
    }
}

// ---------------- launch ----------------
extern "C" void kernel_launch(void* const* d_in, const int* in_sizes, int n_in,
                              void* d_out, int out_size) {
    (void)in_sizes; (void)n_in; (void)out_size;
    const float* x    = (const float*)d_in[0];
    const float* g1   = (const float*)d_in[1];
    const float* b1   = (const float*)d_in[2];
    const float* wqkv = (const float*)d_in[3];
    const float* wout = (const float*)d_in[4];
    const float* bout = (const float*)d_in[5];
    const float* g2   = (const float*)d_in[6];
    const float* b2   = (const float*)d_in[7];
    float* y = (float*)d_out;

    cudaFuncSetAttribute(la_pass1_kernel, cudaFuncAttributeMaxDynamicSharedMemorySize,
                         SM1_FLOATS * (int)sizeof(float));
    cudaFuncSetAttribute(la_pass2_kernel, cudaFuncAttributeMaxDynamicSharedMemorySize,
                         SM2_FLOATS * (int)sizeof(float));

    la_zero_kernel<<<33, 256>>>();
    la_pass1_kernel<<<dim3(NPOS / TPB, BB), TPB, SM1_FLOATS * sizeof(float)>>>(x, g1, b1, wqkv);
    la_fold_kernel<<<BB, 256>>>(wout);
    la_pass2_kernel<<<dim3(NPOS / TPB, BB), TPB, SM2_FLOATS * sizeof(float)>>>(bout, g2, b2, y);
}